// round 1
// baseline (speedup 1.0000x reference)
#include <cuda_runtime.h>
#include <cstdint>

#define NLVL 16
#define TSZ (1 << 19)
#define TMASK ((1u << 19) - 1u)
#define PRIME_Y 2654435761u
#define PRIME_Z 805459861u

__global__ __launch_bounds__(256, 1) void hash_embed_kernel(
    const float* __restrict__ x,
    const float* __restrict__ emb,
    float* __restrict__ out,
    int B)
{
    int b = blockIdx.x * blockDim.x + threadIdx.x;
    if (b >= B) return;

    const float p0 = x[3 * b + 0];
    const float p1 = x[3 * b + 1];
    const float p2 = x[3 * b + 2];

    float acc[2 * NLVL];

    // floor(16 * 2^(i/3)); ambiguous i=3,6,9,12,15 resolved to the
    // power-of-two branch (flip all five to -1 if bench rel_err ~0.3).
    const int RESS[NLVL] = {16, 20, 25, 32, 40, 50, 64, 80,
                            101, 128, 161, 203, 256, 322, 406, 512};

    #pragma unroll
    for (int l = 0; l < NLVL; ++l) {
        const int R = RESS[l];
        // rel = (x - GRID_MIN) / grid_size ; grid_size = 2/R
        const float scale = (float)((double)R * 0.5);
        float r0 = (p0 + 1.0f) * scale;
        float r1 = (p1 + 1.0f) * scale;
        float r2 = (p2 + 1.0f) * scale;

        float f0 = floorf(r0);
        float f1 = floorf(r1);
        float f2 = floorf(r2);
        const float rmax = (float)(R - 1);
        f0 = fminf(fmaxf(f0, 0.0f), rmax);
        f1 = fminf(fmaxf(f1, 0.0f), rmax);
        f2 = fminf(fmaxf(f2, 0.0f), rmax);

        const float w0 = r0 - f0;
        const float w1 = r1 - f1;
        const float w2 = r2 - f2;
        const float u0 = 1.0f - w0;
        const float u1 = 1.0f - w1;
        const float u2 = 1.0f - w2;

        const uint32_t i0 = (uint32_t)f0;
        const uint32_t i1 = (uint32_t)f1;
        const uint32_t i2 = (uint32_t)f2;

        const uint32_t xa = i0;                  // prime 1
        const uint32_t xb = i0 + 1u;
        const uint32_t ya = i1 * PRIME_Y;
        const uint32_t yb = ya + PRIME_Y;
        const uint32_t za = i2 * PRIME_Z;
        const uint32_t zb = za + PRIME_Z;

        const float2* __restrict__ tab =
            reinterpret_cast<const float2*>(emb) + (size_t)l * TSZ;

        // 8 independent gathers (keep MLP high; let ptxas batch them)
        const float2 v000 = __ldg(&tab[(xa ^ ya ^ za) & TMASK]);
        const float2 v100 = __ldg(&tab[(xb ^ ya ^ za) & TMASK]);
        const float2 v010 = __ldg(&tab[(xa ^ yb ^ za) & TMASK]);
        const float2 v110 = __ldg(&tab[(xb ^ yb ^ za) & TMASK]);
        const float2 v001 = __ldg(&tab[(xa ^ ya ^ zb) & TMASK]);
        const float2 v101 = __ldg(&tab[(xb ^ ya ^ zb) & TMASK]);
        const float2 v011 = __ldg(&tab[(xa ^ yb ^ zb) & TMASK]);
        const float2 v111 = __ldg(&tab[(xb ^ yb ^ zb) & TMASK]);

        const float w000 = u0 * u1 * u2;
        const float w100 = w0 * u1 * u2;
        const float w010 = u0 * w1 * u2;
        const float w110 = w0 * w1 * u2;
        const float w001 = u0 * u1 * w2;
        const float w101 = w0 * u1 * w2;
        const float w011 = u0 * w1 * w2;
        const float w111 = w0 * w1 * w2;

        float a0 = w000 * v000.x;
        float a1 = w000 * v000.y;
        a0 = fmaf(w100, v100.x, a0);  a1 = fmaf(w100, v100.y, a1);
        a0 = fmaf(w010, v010.x, a0);  a1 = fmaf(w010, v010.y, a1);
        a0 = fmaf(w110, v110.x, a0);  a1 = fmaf(w110, v110.y, a1);
        a0 = fmaf(w001, v001.x, a0);  a1 = fmaf(w001, v001.y, a1);
        a0 = fmaf(w101, v101.x, a0);  a1 = fmaf(w101, v101.y, a1);
        a0 = fmaf(w011, v011.x, a0);  a1 = fmaf(w011, v011.y, a1);
        a0 = fmaf(w111, v111.x, a0);  a1 = fmaf(w111, v111.y, a1);

        acc[2 * l + 0] = a0;
        acc[2 * l + 1] = a1;
    }

    // 32 contiguous floats per point -> 8x STG.128; warp covers 4 KB
    // contiguous, sectors fill from in-flight stores (no write amp).
    float4* __restrict__ o = reinterpret_cast<float4*>(out) + (size_t)b * 8;
    #pragma unroll
    for (int i = 0; i < 8; ++i) {
        o[i] = make_float4(acc[4 * i + 0], acc[4 * i + 1],
                           acc[4 * i + 2], acc[4 * i + 3]);
    }
}

extern "C" void kernel_launch(void* const* d_in, const int* in_sizes, int n_in,
                              void* d_out, int out_size)
{
    const float* x   = (const float*)d_in[0];   // (B, 3) f32
    const float* emb = (const float*)d_in[1];   // (16, 2^19, 2) f32
    float* out = (float*)d_out;                 // (B, 32) f32

    const int B = in_sizes[0] / 3;
    const int threads = 256;
    const int blocks = (B + threads - 1) / threads;
    hash_embed_kernel<<<blocks, threads>>>(x, emb, out, B);
}